// round 3
// baseline (speedup 1.0000x reference)
#include <cuda_runtime.h>
#include <cstdint>
#include <cstddef>

#define B_   16
#define D_   1024
#define T_   4096
#define CS_  1024
#define CD_  8
#define TILE_T 128
#define NBLK (B_ * T_ / TILE_T)           /* 512 */
#define OUT_ELEMS ((size_t)B_ * D_ * T_)  /* 67108864 */
#define IDX_OFF   OUT_ELEMS
#define LOSS_OFF  (OUT_ELEMS + (size_t)B_ * T_)

// ---------------- device-global scratch (no allocs allowed) ----------------
__device__ float d_Win[D_ * CD_];    // W_in transposed: [d][c], row-contiguous 8
__device__ float d_Cbn[CS_ * CD_];   // normalized codebook rows [code][c]
__device__ float d_Wout[D_ * CD_];   // W_out rows [d][c]
__device__ float d_partial[NBLK];    // per-block commit-loss partial sums

// ---------------- prep: weight-norm + codebook normalization ----------------
__global__ void fvq_prep_kernel(const float* __restrict__ cb,
                                const float* __restrict__ g_in,
                                const float* __restrict__ v_in,
                                const float* __restrict__ g_out,
                                const float* __restrict__ v_out) {
    __shared__ float rin[CD_];
    int tid = threadIdx.x, w = tid >> 5, lane = tid & 31;

    // W_in row norms: 8 warps, one row each (reduce over D=1024)
    if (w < CD_) {
        float s = 0.f;
        for (int i = lane; i < D_; i += 32) {
            float v = v_in[w * D_ + i];
            s += v * v;
        }
        #pragma unroll
        for (int o = 16; o; o >>= 1) s += __shfl_xor_sync(0xffffffffu, s, o);
        if (lane == 0) rin[w] = g_in[w] / fmaxf(sqrtf(s), 1e-12f);
    }
    __syncthreads();

    // Transposed normalized W_in: d_Win[d*8+c] = v_in[c,d] * g_in[c]/||v_in[c,:]||
    for (int i = tid; i < D_ * CD_; i += blockDim.x) {
        int d = i >> 3, c = i & 7;
        d_Win[i] = v_in[c * D_ + d] * rin[c];
    }

    // Normalized codebook rows
    for (int r = tid; r < CS_; r += blockDim.x) {
        float vv[8], n = 0.f;
        #pragma unroll
        for (int c = 0; c < 8; c++) { vv[c] = cb[r * 8 + c]; n += vv[c] * vv[c]; }
        float rn = 1.f / fmaxf(sqrtf(n), 1e-12f);
        #pragma unroll
        for (int c = 0; c < 8; c++) d_Cbn[r * 8 + c] = vv[c] * rn;
    }

    // Normalized W_out rows: d_Wout[d*8+c] = v_out[d,c] * g_out[d]/||v_out[d,:]||
    for (int r = tid; r < D_; r += blockDim.x) {
        float vv[8], n = 0.f;
        #pragma unroll
        for (int c = 0; c < 8; c++) { vv[c] = v_out[r * 8 + c]; n += vv[c] * vv[c]; }
        float sc = g_out[r] / fmaxf(sqrtf(n), 1e-12f);
        #pragma unroll
        for (int c = 0; c < 8; c++) d_Wout[r * 8 + c] = vv[c] * sc;
    }
}

// ---------------- fused main kernel ----------------
// Block = 512 threads = 4 D/CS slices x 128 tokens. Block owns one (b, 128-token) tile.
__global__ void __launch_bounds__(512, 2)
fvq_main_kernel(const float* __restrict__ z,
                const float* __restrict__ cb,
                const float* __restrict__ b_in,
                const float* __restrict__ b_out,
                float* __restrict__ out) {
    __shared__ float sCbn[CS_ * CD_];   // 32 KB, broadcast reads
    __shared__ float sRed[512 * 8];     // 16 KB, partial-sum / argmax exchange

    int tid = threadIdx.x;
    int j = tid & (TILE_T - 1);         // token within tile
    int s = tid >> 7;                   // slice 0..3
    int b = blockIdx.x >> 5;            // 32 blocks per batch
    int t = ((blockIdx.x & 31) * TILE_T) + j;

    for (int i = tid; i < CS_ * CD_; i += 512) sCbn[i] = d_Cbn[i];
    __syncthreads();

    // ---- Phase 1: z_e partial = W_in[slice] . z[b, slice, t] ----
    const float* zp = z + ((size_t)b * D_ + s * 256) * T_ + t;
    const float4* Wt = (const float4*)d_Win + (size_t)(s * 256) * 2;
    float ze[8] = {0.f, 0.f, 0.f, 0.f, 0.f, 0.f, 0.f, 0.f};
    #pragma unroll 4
    for (int d0 = 0; d0 < 256; d0++) {
        float v = __ldg(zp + (size_t)d0 * T_);
        float4 w0 = Wt[d0 * 2];
        float4 w1 = Wt[d0 * 2 + 1];
        ze[0] = fmaf(w0.x, v, ze[0]);
        ze[1] = fmaf(w0.y, v, ze[1]);
        ze[2] = fmaf(w0.z, v, ze[2]);
        ze[3] = fmaf(w0.w, v, ze[3]);
        ze[4] = fmaf(w1.x, v, ze[4]);
        ze[5] = fmaf(w1.y, v, ze[5]);
        ze[6] = fmaf(w1.z, v, ze[6]);
        ze[7] = fmaf(w1.w, v, ze[7]);
    }
    // publish partials, rebuild full z_e in every thread of the token
    {
        float4* sR4 = (float4*)sRed;
        sR4[tid * 2 + 0] = make_float4(ze[0], ze[1], ze[2], ze[3]);
        sR4[tid * 2 + 1] = make_float4(ze[4], ze[5], ze[6], ze[7]);
    }
    __syncthreads();
    float zef[8];
    #pragma unroll
    for (int c = 0; c < 8; c++) zef[c] = b_in[c];
    {
        const float4* sR4 = (const float4*)sRed;
        #pragma unroll
        for (int s2 = 0; s2 < 4; s2++) {
            float4 a = sR4[(s2 * 128 + j) * 2 + 0];
            float4 c4 = sR4[(s2 * 128 + j) * 2 + 1];
            zef[0] += a.x;  zef[1] += a.y;  zef[2] += a.z;  zef[3] += a.w;
            zef[4] += c4.x; zef[5] += c4.y; zef[6] += c4.z; zef[7] += c4.w;
        }
    }

    // ---- Phase 2: nearest neighbor (max z_e . cb_n over this thread's 256 codes) ----
    const float4* cbn4 = (const float4*)sCbn + (size_t)(s * 256) * 2;
    float best = __int_as_float(0xff800000);  // -inf
    int bidx = 0;
    #pragma unroll 4
    for (int cc = 0; cc < 256; cc++) {
        float4 q0 = cbn4[cc * 2];
        float4 q1 = cbn4[cc * 2 + 1];
        float sc = zef[0] * q0.x;
        sc = fmaf(zef[1], q0.y, sc);
        sc = fmaf(zef[2], q0.z, sc);
        sc = fmaf(zef[3], q0.w, sc);
        sc = fmaf(zef[4], q1.x, sc);
        sc = fmaf(zef[5], q1.y, sc);
        sc = fmaf(zef[6], q1.z, sc);
        sc = fmaf(zef[7], q1.w, sc);
        if (sc > best) { best = sc; bidx = cc; }
    }
    int gidx = s * 256 + bidx;

    __syncthreads();  // sRed partial reads done everywhere; safe to reuse
    {
        float2* sArg = (float2*)sRed;
        sArg[tid] = make_float2(best, __int_as_float(gidx));
    }
    __syncthreads();
    float fbest = __int_as_float(0xff800000);
    int fidx = 0;
    {
        const float2* sArg = (const float2*)sRed;
        #pragma unroll
        for (int s2 = 0; s2 < 4; s2++) {   // ascending index order -> first max wins (argmax tie rule)
            float2 cnd = sArg[s2 * 128 + j];
            if (cnd.x > fbest) { fbest = cnd.x; fidx = __float_as_int(cnd.y); }
        }
    }

    // gather raw codebook row (hot 32 KB table, L1/L2)
    const float4* cr = (const float4*)(cb + (size_t)fidx * 8);
    float4 zq0 = __ldg(cr);
    float4 zq1 = __ldg(cr + 1);

    // ---- commit-loss contribution + index output (one thread per token) ----
    float lsum = 0.f;
    if (s == 0) {
        float q[8] = { zq0.x, zq0.y, zq0.z, zq0.w, zq1.x, zq1.y, zq1.z, zq1.w };
        #pragma unroll
        for (int c = 0; c < 8; c++) { float d = zef[c] - q[c]; lsum = fmaf(d, d, lsum); }
        out[IDX_OFF + (size_t)b * T_ + t] = (float)fidx;
    }

    // ---- Phase 3: out[b, slice, t] = W_out[slice] . z_q + b_out ----
    const float4* Wo = (const float4*)d_Wout + (size_t)(s * 256) * 2;
    const float* bo = b_out + s * 256;
    float* op = out + ((size_t)b * D_ + s * 256) * T_ + t;
    #pragma unroll 4
    for (int d0 = 0; d0 < 256; d0++) {
        float4 w0 = Wo[d0 * 2];
        float4 w1 = Wo[d0 * 2 + 1];
        float acc = bo[d0];
        acc = fmaf(zq0.x, w0.x, acc);
        acc = fmaf(zq0.y, w0.y, acc);
        acc = fmaf(zq0.z, w0.z, acc);
        acc = fmaf(zq0.w, w0.w, acc);
        acc = fmaf(zq1.x, w1.x, acc);
        acc = fmaf(zq1.y, w1.y, acc);
        acc = fmaf(zq1.z, w1.z, acc);
        acc = fmaf(zq1.w, w1.w, acc);
        op[(size_t)d0 * T_] = acc;
    }

    // ---- deterministic block-level loss reduction ----
    __syncthreads();  // sArg reads done; reuse sRed
    #pragma unroll
    for (int o = 16; o; o >>= 1) lsum += __shfl_xor_sync(0xffffffffu, lsum, o);
    if ((tid & 31) == 0) sRed[tid >> 5] = lsum;
    __syncthreads();
    if (tid == 0) {
        float tot = 0.f;
        #pragma unroll
        for (int w = 0; w < 16; w++) tot += sRed[w];
        d_partial[blockIdx.x] = tot;
    }
}

// ---------------- final: deterministic per-batch loss ----------------
__global__ void fvq_loss_kernel(float* __restrict__ out) {
    int b = threadIdx.x;
    if (b < B_) {
        float s = 0.f;
        #pragma unroll
        for (int i = 0; i < 32; i++) s += d_partial[b * 32 + i];
        out[LOSS_OFF + b] = s * (1.25f / (float)(CD_ * T_));
    }
}

extern "C" void kernel_launch(void* const* d_in, const int* in_sizes, int n_in,
                              void* d_out, int out_size) {
    (void)in_sizes; (void)n_in; (void)out_size;
    const float* z     = (const float*)d_in[0];
    const float* cb    = (const float*)d_in[1];
    const float* g_in  = (const float*)d_in[2];
    const float* v_in  = (const float*)d_in[3];
    const float* b_in  = (const float*)d_in[4];
    const float* g_out = (const float*)d_in[5];
    const float* v_out = (const float*)d_in[6];
    const float* b_out = (const float*)d_in[7];
    float* out = (float*)d_out;

    fvq_prep_kernel<<<1, 256>>>(cb, g_in, v_in, g_out, v_out);
    fvq_main_kernel<<<NBLK, 512>>>(z, cb, b_in, b_out, out);
    fvq_loss_kernel<<<1, 32>>>(out);
}